// round 2
// baseline (speedup 1.0000x reference)
#include <cuda_runtime.h>
#include <cstdint>

#define B_  2
#define T_  2048
#define D_  1024
#define F_  4096
#define H_  8
#define DH_ 128
#define M_  (B_*T_)          // 4096 rows
#define X_ELEMS (M_*D_)      // 4194304
#define ST_ELEMS (B_*H_*DH_*DH_) // 262144

// ---------------- scratch (static device memory; no allocation at runtime) ----
static __device__ float g_xn[M_*D_];
static __device__ float g_q [M_*D_];
static __device__ float g_k [M_*D_];
static __device__ float g_v [M_*D_];
static __device__ float g_o [M_*D_];
static __device__ float g_ba[M_*H_*2];
static __device__ float g_h1[M_*F_];
static __device__ float g_h2[M_*F_];

__device__ __forceinline__ float silu_f(float x){ return x / (1.0f + expf(-x)); }
__device__ __forceinline__ float sigmoid_f(float x){ return 1.0f / (1.0f + expf(-x)); }

// ---------------- copy: y = x (residual seed) --------------------------------
__global__ __launch_bounds__(256) void copy_k(const float* __restrict__ in,
                                              float* __restrict__ out, int n4)
{
    int i = blockIdx.x * blockDim.x + threadIdx.x;
    if (i < n4) ((float4*)out)[i] = ((const float4*)in)[i];
}

// ---------------- RMSNorm over rows of 1024 ----------------------------------
__global__ __launch_bounds__(256) void rmsnorm_k(const float* __restrict__ in,
                                                 float* __restrict__ out)
{
    int row = blockIdx.x;
    int tid = threadIdx.x;
    const float4* ip = (const float4*)(in + (size_t)row * D_);
    float4 v = ip[tid];
    float ss = v.x*v.x + v.y*v.y + v.z*v.z + v.w*v.w;
    #pragma unroll
    for (int m = 16; m > 0; m >>= 1) ss += __shfl_xor_sync(0xffffffffu, ss, m);
    __shared__ float sred[8];
    if ((tid & 31) == 0) sred[tid >> 5] = ss;
    __syncthreads();
    float tot = 0.f;
    #pragma unroll
    for (int i = 0; i < 8; i++) tot += sred[i];
    float sc = rsqrtf(tot * (1.0f / D_) + 1e-6f);
    float4 o; o.x = v.x*sc; o.y = v.y*sc; o.z = v.z*sc; o.w = v.w*sc;
    ((float4*)(out + (size_t)row * D_))[tid] = o;
}

// ---------------- SGEMM: C[M,N] = A[M,K] @ B[K,N]  (row-major, fp32) ---------
// 128x128 tile, BK=8, 256 threads, 8x8 per thread, double-buffered smem.
// mode==1: C += acc (accumulate into existing C).
__global__ __launch_bounds__(256) void sgemm_k(const float* __restrict__ A,
                                               const float* __restrict__ B,
                                               float* __restrict__ C,
                                               int M, int N, int K, int mode)
{
    __shared__ float As[2][8][128];
    __shared__ float Bs[2][8][128];

    int tid = threadIdx.x;
    int bx = blockIdx.x, by = blockIdx.y;

    int arow = tid >> 1;            // 0..127
    int acol = (tid & 1) * 4;       // 0 or 4
    int brow = tid >> 5;            // 0..7
    int bcol = (tid & 31) * 4;      // 0..124

    const float* Ag = A + ((size_t)(by*128 + arow)) * K + acol;
    const float* Bg = B + (size_t)brow * N + (size_t)bx*128 + bcol;

    float4 av = *(const float4*)Ag;
    float4 bv = *(const float4*)Bg;
    As[0][acol+0][arow] = av.x; As[0][acol+1][arow] = av.y;
    As[0][acol+2][arow] = av.z; As[0][acol+3][arow] = av.w;
    *(float4*)&Bs[0][brow][bcol] = bv;
    __syncthreads();

    int tx = tid & 15, ty = tid >> 4;
    float acc[8][8];
    #pragma unroll
    for (int i = 0; i < 8; i++)
        #pragma unroll
        for (int j = 0; j < 8; j++) acc[i][j] = 0.f;

    int nk = K >> 3;
    for (int kt = 0; kt < nk; kt++) {
        int cur = kt & 1;
        if (kt + 1 < nk) {
            av = *(const float4*)(Ag + (size_t)(kt+1)*8);
            bv = *(const float4*)(Bg + (size_t)(kt+1)*8*N);
        }
        #pragma unroll
        for (int kk = 0; kk < 8; kk++) {
            float a[8], b[8];
            *(float4*)(a)   = *(const float4*)&As[cur][kk][ty*8];
            *(float4*)(a+4) = *(const float4*)&As[cur][kk][ty*8+4];
            *(float4*)(b)   = *(const float4*)&Bs[cur][kk][tx*8];
            *(float4*)(b+4) = *(const float4*)&Bs[cur][kk][tx*8+4];
            #pragma unroll
            for (int i = 0; i < 8; i++)
                #pragma unroll
                for (int j = 0; j < 8; j++) acc[i][j] += a[i] * b[j];
        }
        if (kt + 1 < nk) {
            int nxt = cur ^ 1;
            As[nxt][acol+0][arow] = av.x; As[nxt][acol+1][arow] = av.y;
            As[nxt][acol+2][arow] = av.z; As[nxt][acol+3][arow] = av.w;
            *(float4*)&Bs[nxt][brow][bcol] = bv;
            __syncthreads();
        }
    }

    int cy = by*128 + ty*8;
    int cx = bx*128 + tx*8;
    #pragma unroll
    for (int i = 0; i < 8; i++) {
        float4* cp = (float4*)(C + (size_t)(cy+i)*N + cx);
        float4 r0, r1;
        r0.x = acc[i][0]; r0.y = acc[i][1]; r0.z = acc[i][2]; r0.w = acc[i][3];
        r1.x = acc[i][4]; r1.y = acc[i][5]; r1.z = acc[i][6]; r1.w = acc[i][7];
        if (mode) {
            float4 o0 = cp[0], o1 = cp[1];
            r0.x += o0.x; r0.y += o0.y; r0.z += o0.z; r0.w += o0.w;
            r1.x += o1.x; r1.y += o1.y; r1.z += o1.z; r1.w += o1.w;
        }
        cp[0] = r0; cp[1] = r1;
    }
}

// ---------------- beta/alpha projection: sigmoid(xn @ wb), sigmoid(xn @ wg) --
__global__ __launch_bounds__(128) void bgproj_k(const float* __restrict__ xn,
                                                const float* __restrict__ wb,
                                                const float* __restrict__ wg,
                                                float* __restrict__ ba)
{
    int m = blockIdx.x;
    int tid = threadIdx.x;
    float accb[8], accg[8];
    #pragma unroll
    for (int j = 0; j < 8; j++) { accb[j] = 0.f; accg[j] = 0.f; }

    const float* xr = xn + (size_t)m * D_ + tid*8;
    #pragma unroll
    for (int u = 0; u < 8; u++) {
        float xv = xr[u];
        int krow = tid*8 + u;
        const float4* wbp = (const float4*)(wb + (size_t)krow * H_);
        const float4* wgp = (const float4*)(wg + (size_t)krow * H_);
        float4 b0 = wbp[0], b1 = wbp[1];
        float4 g0 = wgp[0], g1 = wgp[1];
        accb[0] += xv*b0.x; accb[1] += xv*b0.y; accb[2] += xv*b0.z; accb[3] += xv*b0.w;
        accb[4] += xv*b1.x; accb[5] += xv*b1.y; accb[6] += xv*b1.z; accb[7] += xv*b1.w;
        accg[0] += xv*g0.x; accg[1] += xv*g0.y; accg[2] += xv*g0.z; accg[3] += xv*g0.w;
        accg[4] += xv*g1.x; accg[5] += xv*g1.y; accg[6] += xv*g1.z; accg[7] += xv*g1.w;
    }
    __shared__ float red[16][128];
    #pragma unroll
    for (int j = 0; j < 8; j++) { red[j][tid] = accb[j]; red[8+j][tid] = accg[j]; }
    __syncthreads();
    if (tid < 16) {
        float s = 0.f;
        for (int i = 0; i < 128; i++) s += red[tid][i];
        float val = sigmoid_f(s);
        int h = tid & 7;
        int which = tid >> 3;   // 0 = beta (wb), 1 = alpha (wg)
        ba[((size_t)m * H_ + h)*2 + which] = val;
    }
}

// ---------------- silu (+optional per-head L2 norm) on rows of 128 -----------
__global__ __launch_bounds__(256) void silul2_k(float* __restrict__ data, int do_norm)
{
    int row = blockIdx.x * 8 + (threadIdx.x >> 5);
    int lane = threadIdx.x & 31;
    float4* p = (float4*)(data + (size_t)row * DH_) + lane;
    float4 x = *p;
    float4 s;
    s.x = silu_f(x.x); s.y = silu_f(x.y); s.z = silu_f(x.z); s.w = silu_f(x.w);
    if (do_norm) {
        float ss = s.x*s.x + s.y*s.y + s.z*s.z + s.w*s.w;
        #pragma unroll
        for (int m = 16; m > 0; m >>= 1) ss += __shfl_xor_sync(0xffffffffu, ss, m);
        float sc = rsqrtf(ss + 1e-6f);
        s.x *= sc; s.y *= sc; s.z *= sc; s.w *= sc;
    }
    *p = s;
}

// ---------------- gated DeltaNet recurrence ----------------------------------
// Columns of S are independent: grid (16 col-chunks, H, B), 128 threads.
// Warp = 2 columns x 16 row-groups (8 rows each). State register-resident.
// o_v = q.(alpha S) + (q.k) dv  -> one state pass + 3 concurrent reductions.
__global__ __launch_bounds__(128) void deltarec_k(const float* __restrict__ q,
                                                  const float* __restrict__ k,
                                                  const float* __restrict__ v,
                                                  const float* __restrict__ ba,
                                                  const float* __restrict__ s0,
                                                  float* __restrict__ o,
                                                  float* __restrict__ sout)
{
    int b = blockIdx.z, h = blockIdx.y, chunk = blockIdx.x;
    int tid = threadIdx.x;
    int warp = tid >> 5, lane = tid & 31;
    int grp = lane >> 4;       // column within warp
    int idx = lane & 15;       // row group
    int col = chunk*8 + warp*2 + grp;
    int r0  = idx * 8;

    float s[8];
    {
        const float* sp = s0 + (((size_t)(b*H_ + h)*DH_) + r0)*DH_ + col;
        #pragma unroll
        for (int i = 0; i < 8; i++) s[i] = sp[(size_t)i * DH_];
    }

    size_t off = (size_t)b * T_ * (H_*DH_) + (size_t)h * DH_;   // + t*1024 + d
    const float* kp  = k  + off + r0;
    const float* qp  = q  + off + r0;
    const float* vp  = v  + off + col;
    const float* bap = ba + ((size_t)b * T_) * (H_*2) + h*2;    // + t*16

    float4 k0 = *(const float4*)(kp);
    float4 k1 = *(const float4*)(kp + 4);
    float4 q0 = *(const float4*)(qp);
    float4 q1 = *(const float4*)(qp + 4);
    float vv = *vp;
    float bb = bap[0];
    float aa = bap[1];

    for (int t = 0; t < T_; t++) {
        int tn = (t + 1 < T_) ? t + 1 : t;
        // prefetch next step while this step computes
        float4 nk0 = *(const float4*)(kp + (size_t)tn*1024);
        float4 nk1 = *(const float4*)(kp + (size_t)tn*1024 + 4);
        float4 nq0 = *(const float4*)(qp + (size_t)tn*1024);
        float4 nq1 = *(const float4*)(qp + (size_t)tn*1024 + 4);
        float nvv  = vp [(size_t)tn*1024];
        float nbb  = bap[(size_t)tn*16];
        float naa  = bap[(size_t)tn*16 + 1];

        float kr[8] = {k0.x,k0.y,k0.z,k0.w,k1.x,k1.y,k1.z,k1.w};
        float qr[8] = {q0.x,q0.y,q0.z,q0.w,q1.x,q1.y,q1.z,q1.w};

        float pred = 0.f, po = 0.f, qk = 0.f;
        #pragma unroll
        for (int i = 0; i < 8; i++) {
            float sv = s[i] * aa;    // gated decay
            s[i] = sv;
            pred += kr[i] * sv;
            po   += qr[i] * sv;
            qk   += kr[i] * qr[i];
        }
        #pragma unroll
        for (int m = 1; m < 16; m <<= 1) {
            pred += __shfl_xor_sync(0xffffffffu, pred, m);
            po   += __shfl_xor_sync(0xffffffffu, po,   m);
            qk   += __shfl_xor_sync(0xffffffffu, qk,   m);
        }
        float dv = bb * (vv - pred);
        float ov = po + qk * dv;
        #pragma unroll
        for (int i = 0; i < 8; i++) s[i] += kr[i] * dv;   // rank-1 write

        if (idx == 0) o[off + (size_t)t*1024 + col] = ov;

        k0 = nk0; k1 = nk1; q0 = nq0; q1 = nq1;
        vv = nvv; bb = nbb; aa = naa;
    }

    float* sp = sout + (((size_t)(b*H_ + h)*DH_) + r0)*DH_ + col;
    #pragma unroll
    for (int i = 0; i < 8; i++) sp[(size_t)i * DH_] = s[i];
}

// ---------------- g = silu(h1) * h2 (in place into h1) -----------------------
__global__ __launch_bounds__(256) void silumul_k(float* __restrict__ h1,
                                                 const float* __restrict__ h2,
                                                 int n4)
{
    for (int i = blockIdx.x * blockDim.x + threadIdx.x; i < n4;
         i += gridDim.x * blockDim.x) {
        float4 a = ((float4*)h1)[i];
        float4 b = ((const float4*)h2)[i];
        a.x = silu_f(a.x) * b.x;
        a.y = silu_f(a.y) * b.y;
        a.z = silu_f(a.z) * b.z;
        a.w = silu_f(a.w) * b.w;
        ((float4*)h1)[i] = a;
    }
}

// ---------------- launcher ----------------------------------------------------
struct Scratch {
    float *xn, *q, *k, *v, *o, *ba, *h1, *h2;
    bool init = false;
};
static Scratch g_sc;

extern "C" void kernel_launch(void* const* d_in, const int* in_sizes, int n_in,
                              void* d_out, int out_size)
{
    const float* x   = (const float*)d_in[0];
    const float* st0 = (const float*)d_in[1];
    const float* wq  = (const float*)d_in[2];
    const float* wk  = (const float*)d_in[3];
    const float* wv  = (const float*)d_in[4];
    const float* wb  = (const float*)d_in[5];
    const float* wg  = (const float*)d_in[6];
    const float* wo  = (const float*)d_in[7];
    const float* wgate = (const float*)d_in[8];
    const float* wup   = (const float*)d_in[9];
    const float* wdown = (const float*)d_in[10];

    float* out = (float*)d_out;            // [x (4194304) | new_state (262144)]
    float* y   = out;                       // residual stream lives in d_out
    float* stO = out + X_ELEMS;

    if (!g_sc.init) {
        cudaGetSymbolAddress((void**)&g_sc.xn, g_xn);
        cudaGetSymbolAddress((void**)&g_sc.q,  g_q);
        cudaGetSymbolAddress((void**)&g_sc.k,  g_k);
        cudaGetSymbolAddress((void**)&g_sc.v,  g_v);
        cudaGetSymbolAddress((void**)&g_sc.o,  g_o);
        cudaGetSymbolAddress((void**)&g_sc.ba, g_ba);
        cudaGetSymbolAddress((void**)&g_sc.h1, g_h1);
        cudaGetSymbolAddress((void**)&g_sc.h2, g_h2);
        g_sc.init = true;
    }
    float *xn = g_sc.xn, *qb = g_sc.q, *kb = g_sc.k, *vb = g_sc.v;
    float *ob = g_sc.o, *bab = g_sc.ba, *h1 = g_sc.h1, *h2 = g_sc.h2;

    // 1) xn = rmsnorm(x)
    rmsnorm_k<<<M_, 256>>>(x, xn);

    // 2) projections
    sgemm_k<<<dim3(D_/128, M_/128), 256>>>(xn, wq, qb, M_, D_, D_, 0);
    sgemm_k<<<dim3(D_/128, M_/128), 256>>>(xn, wk, kb, M_, D_, D_, 0);
    sgemm_k<<<dim3(D_/128, M_/128), 256>>>(xn, wv, vb, M_, D_, D_, 0);
    bgproj_k<<<M_, 128>>>(xn, wb, wg, bab);

    // 3) silu + per-head L2 norm (q,k); silu (v)
    silul2_k<<<(M_*H_)/8, 256>>>(qb, 1);
    silul2_k<<<(M_*H_)/8, 256>>>(kb, 1);
    silul2_k<<<(M_*H_)/8, 256>>>(vb, 0);

    // 4) recurrence -> o, final state
    deltarec_k<<<dim3(16, H_, B_), 128>>>(qb, kb, vb, bab, st0, ob, stO);

    // 5) y = x; y += o @ wo
    copy_k<<<(X_ELEMS/4 + 255)/256, 256>>>(x, y, X_ELEMS/4);
    sgemm_k<<<dim3(D_/128, M_/128), 256>>>(ob, wo, y, M_, D_, D_, 1);

    // 6) yn = rmsnorm(y); h1 = yn@w_gate; h2 = yn@w_up
    rmsnorm_k<<<M_, 256>>>(y, xn);
    sgemm_k<<<dim3(F_/128, M_/128), 256>>>(xn, wgate, h1, M_, F_, D_, 0);
    sgemm_k<<<dim3(F_/128, M_/128), 256>>>(xn, wup,   h2, M_, F_, D_, 0);

    // 7) h1 = silu(h1)*h2 ; out = y + h1 @ w_down
    silumul_k<<<4096, 256>>>(h1, h2, (M_*F_)/4);
    sgemm_k<<<dim3(D_/128, M_/128), 256>>>(h1, wdown, y, M_, D_, F_, 1);
}

// round 4
// speedup vs baseline: 1.7522x; 1.7522x over previous
#include <cuda_runtime.h>
#include <cuda_bf16.h>
#include <cstdint>

#define B_  2
#define T_  2048
#define D_  1024
#define F_  4096
#define H_  8
#define DH_ 128
#define M_  (B_*T_)              // 4096 rows
#define X_ELEMS (M_*D_)          // 4194304

// ---------------- scratch (static device memory; no allocation at runtime) ----
static __device__ float g_xn[M_*D_];
static __device__ float g_q [M_*D_];
static __device__ float g_k [M_*D_];
static __device__ float g_v [M_*D_];
static __device__ float g_o [M_*D_];
static __device__ float g_ba[M_*H_*2];
static __device__ float g_h1[M_*F_];
static __device__ float g_h2[M_*F_];

// bf16 split buffers (hi/lo)
static __device__ __nv_bfloat16 g_xh[M_*F_];   // A operand: xn (4M) / h1 (16M)
static __device__ __nv_bfloat16 g_xl[M_*F_];
static __device__ __nv_bfloat16 g_oh[M_*D_];
static __device__ __nv_bfloat16 g_ol[M_*D_];
static __device__ __nv_bfloat16 g_wqh[D_*D_], g_wql[D_*D_];
static __device__ __nv_bfloat16 g_wkh[D_*D_], g_wkl[D_*D_];
static __device__ __nv_bfloat16 g_wvh[D_*D_], g_wvl[D_*D_];
static __device__ __nv_bfloat16 g_woh[D_*D_], g_wol[D_*D_];
static __device__ __nv_bfloat16 g_wgh[D_*F_], g_wgl[D_*F_];
static __device__ __nv_bfloat16 g_wuh[D_*F_], g_wul[D_*F_];
static __device__ __nv_bfloat16 g_wdh[F_*D_], g_wdl[F_*D_];

__device__ __forceinline__ float silu_f(float x){ return x / (1.0f + expf(-x)); }
__device__ __forceinline__ float sigmoid_f(float x){ return 1.0f / (1.0f + expf(-x)); }

__device__ __forceinline__ uint32_t smem_u32(const void* p) {
    uint32_t a;
    asm("{ .reg .u64 t; cvta.to.shared.u64 t, %1; cvt.u32.u64 %0, t; }" : "=r"(a) : "l"(p));
    return a;
}

// ============================ elementwise / prep kernels ======================
__global__ __launch_bounds__(256) void rmsnorm_k(const float* __restrict__ in,
                                                 float* __restrict__ out)
{
    int row = blockIdx.x;
    int tid = threadIdx.x;
    const float4* ip = (const float4*)(in + (size_t)row * D_);
    float4 v = ip[tid];
    float ss = v.x*v.x + v.y*v.y + v.z*v.z + v.w*v.w;
    #pragma unroll
    for (int m = 16; m > 0; m >>= 1) ss += __shfl_xor_sync(0xffffffffu, ss, m);
    __shared__ float sred[8];
    if ((tid & 31) == 0) sred[tid >> 5] = ss;
    __syncthreads();
    float tot = 0.f;
    #pragma unroll
    for (int i = 0; i < 8; i++) tot += sred[i];
    float sc = rsqrtf(tot * (1.0f / D_) + 1e-6f);
    float4 o; o.x = v.x*sc; o.y = v.y*sc; o.z = v.z*sc; o.w = v.w*sc;
    ((float4*)(out + (size_t)row * D_))[tid] = o;
}

// split fp32 -> bf16 hi + bf16 lo (same layout)
__global__ __launch_bounds__(256) void split_k(const float* __restrict__ in,
                                               __nv_bfloat16* __restrict__ oh,
                                               __nv_bfloat16* __restrict__ ol,
                                               int n4)
{
    for (int i = blockIdx.x * blockDim.x + threadIdx.x; i < n4;
         i += gridDim.x * blockDim.x) {
        float4 v = ((const float4*)in)[i];
        __nv_bfloat16 h0 = __float2bfloat16(v.x);
        __nv_bfloat16 h1 = __float2bfloat16(v.y);
        __nv_bfloat16 h2 = __float2bfloat16(v.z);
        __nv_bfloat16 h3 = __float2bfloat16(v.w);
        __nv_bfloat162 lo0, lo1;
        lo0.x = __float2bfloat16(v.x - __bfloat162float(h0));
        lo0.y = __float2bfloat16(v.y - __bfloat162float(h1));
        lo1.x = __float2bfloat16(v.z - __bfloat162float(h2));
        lo1.y = __float2bfloat16(v.w - __bfloat162float(h3));
        __nv_bfloat162 hi0; hi0.x = h0; hi0.y = h1;
        __nv_bfloat162 hi1; hi1.x = h2; hi1.y = h3;
        ((__nv_bfloat162*)oh)[i*2]   = hi0;
        ((__nv_bfloat162*)oh)[i*2+1] = hi1;
        ((__nv_bfloat162*)ol)[i*2]   = lo0;
        ((__nv_bfloat162*)ol)[i*2+1] = lo1;
    }
}

// transpose [R][Cc] fp32 -> [Cc][R] bf16 hi/lo
__global__ __launch_bounds__(256) void tsplit_k(const float* __restrict__ in,
                                                __nv_bfloat16* __restrict__ oh,
                                                __nv_bfloat16* __restrict__ ol,
                                                int R, int Cc)
{
    __shared__ float t[32][33];
    int tx = threadIdx.x & 31, ty = threadIdx.x >> 5;   // 32x8
    int c0 = blockIdx.x * 32, r0 = blockIdx.y * 32;
    #pragma unroll
    for (int i = 0; i < 4; i++)
        t[ty + i*8][tx] = in[(size_t)(r0 + ty + i*8) * Cc + c0 + tx];
    __syncthreads();
    #pragma unroll
    for (int i = 0; i < 4; i++) {
        int oc = ty + i*8;
        float v = t[tx][oc];
        __nv_bfloat16 h = __float2bfloat16(v);
        __nv_bfloat16 l = __float2bfloat16(v - __bfloat162float(h));
        size_t oi = (size_t)(c0 + oc) * R + r0 + tx;
        oh[oi] = h; ol[oi] = l;
    }
}

// ============================ mma.sync split-bf16 GEMM ========================
// C[M,N] = (addend?) + A[M,K] @ Bt[N,K]^T  via 3-term bf16 split HMMA.
// Tile 128x128, BK=32, 256 threads (8 warps, warp tile 64x32), 2-stage cp.async.
#define RS_   40                      // smem row stride in bf16 elems (80 B)
#define TILE_B (128*RS_*2)            // 10240 B per operand tile
#define HG_SMEM (TILE_B*4*2)          // 4 tensors x 2 stages = 81920 B

__device__ __forceinline__ void ldsm_x4(uint32_t& r0, uint32_t& r1,
                                        uint32_t& r2, uint32_t& r3, uint32_t a) {
    asm volatile("ldmatrix.sync.aligned.m8n8.x4.shared.b16 {%0,%1,%2,%3}, [%4];"
                 : "=r"(r0), "=r"(r1), "=r"(r2), "=r"(r3) : "r"(a));
}
__device__ __forceinline__ void mma16816(float& d0, float& d1, float& d2, float& d3,
                                         uint32_t a0, uint32_t a1, uint32_t a2, uint32_t a3,
                                         uint32_t b0, uint32_t b1) {
    asm volatile("mma.sync.aligned.m16n8k16.row.col.f32.bf16.bf16.f32 "
                 "{%0,%1,%2,%3}, {%4,%5,%6,%7}, {%8,%9}, {%0,%1,%2,%3};"
                 : "+f"(d0), "+f"(d1), "+f"(d2), "+f"(d3)
                 : "r"(a0), "r"(a1), "r"(a2), "r"(a3), "r"(b0), "r"(b1));
}
__device__ __forceinline__ void cp16(uint32_t s, const void* g) {
    asm volatile("cp.async.cg.shared.global [%0], [%1], 16;" :: "r"(s), "l"(g));
}

__global__ __launch_bounds__(256, 1) void hgemm_k(
    const __nv_bfloat16* __restrict__ Ah, const __nv_bfloat16* __restrict__ Al,
    const __nv_bfloat16* __restrict__ Bh, const __nv_bfloat16* __restrict__ Bl,
    const float* __restrict__ addend, float* __restrict__ C,
    int M, int N, int K)
{
    extern __shared__ char smem[];
    uint32_t S0 = smem_u32(smem);

    int tid = threadIdx.x;
    int wid = tid >> 5, lane = tid & 31;
    int m0 = blockIdx.y << 7, n0 = blockIdx.x << 7;

    // cp.async role: seg s = tid&3 (16B within 80B row), row r = tid>>2 (+64)
    int seg = tid & 3, rr = tid >> 2;
    const __nv_bfloat16* gA[4] = { Ah, Al, Bh, Bl };
    int rbase[4] = { m0, m0, n0, n0 };

    int NK = K >> 5;

    // prefetch stage 0
    {
        uint32_t sb = S0;
        #pragma unroll
        for (int ten = 0; ten < 4; ten++) {
            const __nv_bfloat16* G = gA[ten] + (size_t)(rbase[ten] + rr) * K + seg * 8;
            uint32_t sa = sb + ten * TILE_B + rr * 80 + seg * 16;
            cp16(sa, G);
            cp16(sa + 64 * 80, G + (size_t)64 * K);
        }
        asm volatile("cp.async.commit_group;");
    }

    // warp tiling: 2 m-warps x 4 n-warps
    int wm = wid >> 2, wn = wid & 3;
    int m_off = wm * 64, n_off = wn * 32;

    // ldmatrix lane offsets (bytes, within an operand tile)
    uint32_t a_lo = (uint32_t)((lane & 15) * 80 + (lane >> 4) * 16);
    uint32_t b_lo = (uint32_t)(((lane & 7) + ((lane >> 4) << 3)) * 80 + (((lane >> 3) & 1) << 4));

    float acc[4][4][4];
    #pragma unroll
    for (int i = 0; i < 4; i++)
        #pragma unroll
        for (int j = 0; j < 4; j++)
            #pragma unroll
            for (int r = 0; r < 4; r++) acc[i][j][r] = 0.f;

    for (int kt = 0; kt < NK; kt++) {
        int cur = kt & 1;
        if (kt + 1 < NK) {
            int nxt = cur ^ 1;
            int k0 = (kt + 1) << 5;
            uint32_t sb = S0 + nxt * (TILE_B * 4);
            #pragma unroll
            for (int ten = 0; ten < 4; ten++) {
                const __nv_bfloat16* G = gA[ten] + (size_t)(rbase[ten] + rr) * K + k0 + seg * 8;
                uint32_t sa = sb + ten * TILE_B + rr * 80 + seg * 16;
                cp16(sa, G);
                cp16(sa + 64 * 80, G + (size_t)64 * K);
            }
            asm volatile("cp.async.commit_group;");
            asm volatile("cp.async.wait_group 1;");
        } else {
            asm volatile("cp.async.wait_group 0;");
        }
        __syncthreads();

        uint32_t base = S0 + cur * (TILE_B * 4);
        uint32_t tAh = base, tAl = base + TILE_B, tBh = base + 2*TILE_B, tBl = base + 3*TILE_B;

        #pragma unroll
        for (int kk = 0; kk < 2; kk++) {
            uint32_t koff = (uint32_t)(kk * 32);
            uint32_t ah[4][4], al[4][4];
            #pragma unroll
            for (int mi = 0; mi < 4; mi++) {
                uint32_t off = (uint32_t)((m_off + mi*16) * 80) + koff + a_lo;
                ldsm_x4(ah[mi][0], ah[mi][1], ah[mi][2], ah[mi][3], tAh + off);
                ldsm_x4(al[mi][0], al[mi][1], al[mi][2], al[mi][3], tAl + off);
            }
            uint32_t bh[4][2], bl[4][2];
            #pragma unroll
            for (int ni = 0; ni < 2; ni++) {
                uint32_t off = (uint32_t)((n_off + ni*16) * 80) + koff + b_lo;
                uint32_t r0, r1, r2, r3;
                ldsm_x4(r0, r1, r2, r3, tBh + off);
                bh[ni*2][0] = r0; bh[ni*2][1] = r1; bh[ni*2+1][0] = r2; bh[ni*2+1][1] = r3;
                ldsm_x4(r0, r1, r2, r3, tBl + off);
                bl[ni*2][0] = r0; bl[ni*2][1] = r1; bl[ni*2+1][0] = r2; bl[ni*2+1][1] = r3;
            }
            #pragma unroll
            for (int mi = 0; mi < 4; mi++)
                #pragma unroll
                for (int ni = 0; ni < 4; ni++) {
                    mma16816(acc[mi][ni][0], acc[mi][ni][1], acc[mi][ni][2], acc[mi][ni][3],
                             ah[mi][0], ah[mi][1], ah[mi][2], ah[mi][3], bh[ni][0], bh[ni][1]);
                    mma16816(acc[mi][ni][0], acc[mi][ni][1], acc[mi][ni][2], acc[mi][ni][3],
                             ah[mi][0], ah[mi][1], ah[mi][2], ah[mi][3], bl[ni][0], bl[ni][1]);
                    mma16816(acc[mi][ni][0], acc[mi][ni][1], acc[mi][ni][2], acc[mi][ni][3],
                             al[mi][0], al[mi][1], al[mi][2], al[mi][3], bh[ni][0], bh[ni][1]);
                }
        }
        __syncthreads();
    }

    // epilogue
    int rbase_m = m0 + m_off + (lane >> 2);
    int cbase   = n0 + n_off + (lane & 3) * 2;
    #pragma unroll
    for (int mi = 0; mi < 4; mi++) {
        #pragma unroll
        for (int ni = 0; ni < 4; ni++) {
            int row = rbase_m + mi * 16;
            int col = cbase + ni * 8;
            float2 v0 = { acc[mi][ni][0], acc[mi][ni][1] };
            float2 v1 = { acc[mi][ni][2], acc[mi][ni][3] };
            if (addend) {
                float2 a0 = *(const float2*)(addend + (size_t)row * N + col);
                float2 a1 = *(const float2*)(addend + (size_t)(row + 8) * N + col);
                v0.x += a0.x; v0.y += a0.y; v1.x += a1.x; v1.y += a1.y;
            }
            *(float2*)(C + (size_t)row * N + col) = v0;
            *(float2*)(C + (size_t)(row + 8) * N + col) = v1;
        }
    }
}

// ---------------- beta/alpha projection ---------------------------------------
__global__ __launch_bounds__(128) void bgproj_k(const float* __restrict__ xn,
                                                const float* __restrict__ wb,
                                                const float* __restrict__ wg,
                                                float* __restrict__ ba)
{
    int m = blockIdx.x;
    int tid = threadIdx.x;
    float accb[8], accg[8];
    #pragma unroll
    for (int j = 0; j < 8; j++) { accb[j] = 0.f; accg[j] = 0.f; }

    const float* xr = xn + (size_t)m * D_ + tid*8;
    #pragma unroll
    for (int u = 0; u < 8; u++) {
        float xv = xr[u];
        int krow = tid*8 + u;
        const float4* wbp = (const float4*)(wb + (size_t)krow * H_);
        const float4* wgp = (const float4*)(wg + (size_t)krow * H_);
        float4 b0 = wbp[0], b1 = wbp[1];
        float4 g0 = wgp[0], g1 = wgp[1];
        accb[0] += xv*b0.x; accb[1] += xv*b0.y; accb[2] += xv*b0.z; accb[3] += xv*b0.w;
        accb[4] += xv*b1.x; accb[5] += xv*b1.y; accb[6] += xv*b1.z; accb[7] += xv*b1.w;
        accg[0] += xv*g0.x; accg[1] += xv*g0.y; accg[2] += xv*g0.z; accg[3] += xv*g0.w;
        accg[4] += xv*g1.x; accg[5] += xv*g1.y; accg[6] += xv*g1.z; accg[7] += xv*g1.w;
    }
    __shared__ float red[16][128];
    #pragma unroll
    for (int j = 0; j < 8; j++) { red[j][tid] = accb[j]; red[8+j][tid] = accg[j]; }
    __syncthreads();
    if (tid < 16) {
        float s = 0.f;
        for (int i = 0; i < 128; i++) s += red[tid][i];
        float val = sigmoid_f(s);
        int h = tid & 7;
        int which = tid >> 3;
        ba[((size_t)m * H_ + h)*2 + which] = val;
    }
}

// ---------------- silu (+optional per-head L2 norm) ---------------------------
__global__ __launch_bounds__(256) void silul2_k(float* __restrict__ data, int do_norm)
{
    int row = blockIdx.x * 8 + (threadIdx.x >> 5);
    int lane = threadIdx.x & 31;
    float4* p = (float4*)(data + (size_t)row * DH_) + lane;
    float4 x = *p;
    float4 s;
    s.x = silu_f(x.x); s.y = silu_f(x.y); s.z = silu_f(x.z); s.w = silu_f(x.w);
    if (do_norm) {
        float ss = s.x*s.x + s.y*s.y + s.z*s.z + s.w*s.w;
        #pragma unroll
        for (int m = 16; m > 0; m >>= 1) ss += __shfl_xor_sync(0xffffffffu, ss, m);
        float sc = rsqrtf(ss + 1e-6f);
        s.x *= sc; s.y *= sc; s.z *= sc; s.w *= sc;
    }
    *p = s;
}

// ---------------- gated DeltaNet recurrence -----------------------------------
__global__ __launch_bounds__(128) void deltarec_k(const float* __restrict__ q,
                                                  const float* __restrict__ k,
                                                  const float* __restrict__ v,
                                                  const float* __restrict__ ba,
                                                  const float* __restrict__ s0,
                                                  float* __restrict__ o,
                                                  float* __restrict__ sout)
{
    int b = blockIdx.z, h = blockIdx.y, chunk = blockIdx.x;
    int tid = threadIdx.x;
    int warp = tid >> 5, lane = tid & 31;
    int grp = lane >> 4;
    int idx = lane & 15;
    int col = chunk*8 + warp*2 + grp;
    int r0  = idx * 8;

    float s[8];
    {
        const float* sp = s0 + (((size_t)(b*H_ + h)*DH_) + r0)*DH_ + col;
        #pragma unroll
        for (int i = 0; i < 8; i++) s[i] = sp[(size_t)i * DH_];
    }

    size_t off = (size_t)b * T_ * (H_*DH_) + (size_t)h * DH_;
    const float* kp  = k  + off + r0;
    const float* qp  = q  + off + r0;
    const float* vp  = v  + off + col;
    const float* bap = ba + ((size_t)b * T_) * (H_*2) + h*2;

    float4 k0 = *(const float4*)(kp);
    float4 k1 = *(const float4*)(kp + 4);
    float4 q0 = *(const float4*)(qp);
    float4 q1 = *(const float4*)(qp + 4);
    float vv = *vp;
    float bb = bap[0];
    float aa = bap[1];

    for (int t = 0; t < T_; t++) {
        int tn = (t + 1 < T_) ? t + 1 : t;
        float4 nk0 = *(const float4*)(kp + (size_t)tn*1024);
        float4 nk1 = *(const float4*)(kp + (size_t)tn*1024 + 4);
        float4 nq0 = *(const float4*)(qp + (size_t)tn*1024);
        float4 nq1 = *(const float4*)(qp + (size_t)tn*1024 + 4);
        float nvv  = vp [(size_t)tn*1024];
        float nbb  = bap[(size_t)tn*16];
        float naa  = bap[(size_t)tn*16 + 1];

        float kr[8] = {k0.x,k0.y,k0.z,k0.w,k1.x,k1.y,k1.z,k1.w};
        float qr[8] = {q0.x,q0.y,q0.z,q0.w,q1.x,q1.y,q1.z,q1.w};

        float pred = 0.f, po = 0.f, qk = 0.f;
        #pragma unroll
        for (int i = 0; i < 8; i++) {
            float sv = s[i] * aa;
            s[i] = sv;
            pred += kr[i] * sv;
            po   += qr[i] * sv;
            qk   += kr[i] * qr[i];
        }
        #pragma unroll
        for (int m = 1; m < 16; m <<= 1) {
            pred += __shfl_xor_sync(0xffffffffu, pred, m);
            po   += __shfl_xor_sync(0xffffffffu, po,   m);
            qk   += __shfl_xor_sync(0xffffffffu, qk,   m);
        }
        float dv = bb * (vv - pred);
        float ov = po + qk * dv;
        #pragma unroll
        for (int i = 0; i < 8; i++) s[i] += kr[i] * dv;

        if (idx == 0) o[off + (size_t)t*1024 + col] = ov;

        k0 = nk0; k1 = nk1; q0 = nq0; q1 = nq1;
        vv = nvv; bb = nbb; aa = naa;
    }

    float* sp = sout + (((size_t)(b*H_ + h)*DH_) + r0)*DH_ + col;
    #pragma unroll
    for (int i = 0; i < 8; i++) sp[(size_t)i * DH_] = s[i];
}

// ---------------- g = silu(h1) * h2 -------------------------------------------
__global__ __launch_bounds__(256) void silumul_k(float* __restrict__ h1,
                                                 const float* __restrict__ h2,
                                                 int n4)
{
    for (int i = blockIdx.x * blockDim.x + threadIdx.x; i < n4;
         i += gridDim.x * blockDim.x) {
        float4 a = ((float4*)h1)[i];
        float4 b = ((const float4*)h2)[i];
        a.x = silu_f(a.x) * b.x;
        a.y = silu_f(a.y) * b.y;
        a.z = silu_f(a.z) * b.z;
        a.w = silu_f(a.w) * b.w;
        ((float4*)h1)[i] = a;
    }
}

// ---------------- launcher -----------------------------------------------------
struct Ptrs {
    float *xn, *q, *k, *v, *o, *ba, *h1, *h2;
    __nv_bfloat16 *xh, *xl, *oh, *ol;
    __nv_bfloat16 *wqh, *wql, *wkh, *wkl, *wvh, *wvl, *woh, *wol;
    __nv_bfloat16 *wgh, *wgl, *wuh, *wul, *wdh, *wdl;
    bool init = false;
};
static Ptrs P;

extern "C" void kernel_launch(void* const* d_in, const int* in_sizes, int n_in,
                              void* d_out, int out_size)
{
    const float* x   = (const float*)d_in[0];
    const float* st0 = (const float*)d_in[1];
    const float* wq  = (const float*)d_in[2];
    const float* wk  = (const float*)d_in[3];
    const float* wv  = (const float*)d_in[4];
    const float* wb  = (const float*)d_in[5];
    const float* wg  = (const float*)d_in[6];
    const float* wo  = (const float*)d_in[7];
    const float* wgate = (const float*)d_in[8];
    const float* wup   = (const float*)d_in[9];
    const float* wdown = (const float*)d_in[10];

    float* out = (float*)d_out;   // [x (4194304) | new_state (262144)]
    float* y   = out;
    float* stO = out + X_ELEMS;

    if (!P.init) {
        cudaGetSymbolAddress((void**)&P.xn, g_xn);
        cudaGetSymbolAddress((void**)&P.q,  g_q);
        cudaGetSymbolAddress((void**)&P.k,  g_k);
        cudaGetSymbolAddress((void**)&P.v,  g_v);
        cudaGetSymbolAddress((void**)&P.o,  g_o);
        cudaGetSymbolAddress((void**)&P.ba, g_ba);
        cudaGetSymbolAddress((void**)&P.h1, g_h1);
        cudaGetSymbolAddress((void**)&P.h2, g_h2);
        cudaGetSymbolAddress((void**)&P.xh, g_xh);
        cudaGetSymbolAddress((void**)&P.xl, g_xl);
        cudaGetSymbolAddress((void**)&P.oh, g_oh);
        cudaGetSymbolAddress((void**)&P.ol, g_ol);
        cudaGetSymbolAddress((void**)&P.wqh, g_wqh); cudaGetSymbolAddress((void**)&P.wql, g_wql);
        cudaGetSymbolAddress((void**)&P.wkh, g_wkh); cudaGetSymbolAddress((void**)&P.wkl, g_wkl);
        cudaGetSymbolAddress((void**)&P.wvh, g_wvh); cudaGetSymbolAddress((void**)&P.wvl, g_wvl);
        cudaGetSymbolAddress((void**)&P.woh, g_woh); cudaGetSymbolAddress((void**)&P.wol, g_wol);
        cudaGetSymbolAddress((void**)&P.wgh, g_wgh); cudaGetSymbolAddress((void**)&P.wgl, g_wgl);
        cudaGetSymbolAddress((void**)&P.wuh, g_wuh); cudaGetSymbolAddress((void**)&P.wul, g_wul);
        cudaGetSymbolAddress((void**)&P.wdh, g_wdh); cudaGetSymbolAddress((void**)&P.wdl, g_wdl);
        cudaFuncSetAttribute(hgemm_k, cudaFuncAttributeMaxDynamicSharedMemorySize, HG_SMEM);
        P.init = true;
    }

    // weight transposes + bf16 splits:  [R][Cc] -> [Cc][R] hi/lo
    tsplit_k<<<dim3(D_/32, D_/32), 256>>>(wq, P.wqh, P.wql, D_, D_);
    tsplit_k<<<dim3(D_/32, D_/32), 256>>>(wk, P.wkh, P.wkl, D_, D_);
    tsplit_k<<<dim3(D_/32, D_/32), 256>>>(wv, P.wvh, P.wvl, D_, D_);
    tsplit_k<<<dim3(D_/32, D_/32), 256>>>(wo, P.woh, P.wol, D_, D_);
    tsplit_k<<<dim3(F_/32, D_/32), 256>>>(wgate, P.wgh, P.wgl, D_, F_);
    tsplit_k<<<dim3(F_/32, D_/32), 256>>>(wup,   P.wuh, P.wul, D_, F_);
    tsplit_k<<<dim3(D_/32, F_/32), 256>>>(wdown, P.wdh, P.wdl, F_, D_);

    // 1) xn = rmsnorm(x); split
    rmsnorm_k<<<M_, 256>>>(x, P.xn);
    split_k<<<2048, 256>>>(P.xn, P.xh, P.xl, X_ELEMS/4);

    // 2) projections (tensor cores)
    hgemm_k<<<dim3(D_/128, M_/128), 256, HG_SMEM>>>(P.xh, P.xl, P.wqh, P.wql, nullptr, P.q, M_, D_, D_);
    hgemm_k<<<dim3(D_/128, M_/128), 256, HG_SMEM>>>(P.xh, P.xl, P.wkh, P.wkl, nullptr, P.k, M_, D_, D_);
    hgemm_k<<<dim3(D_/128, M_/128), 256, HG_SMEM>>>(P.xh, P.xl, P.wvh, P.wvl, nullptr, P.v, M_, D_, D_);
    bgproj_k<<<M_, 128>>>(P.xn, wb, wg, P.ba);

    // 3) silu + per-head L2 norm (q,k); silu (v)
    silul2_k<<<(M_*H_)/8, 256>>>(P.q, 1);
    silul2_k<<<(M_*H_)/8, 256>>>(P.k, 1);
    silul2_k<<<(M_*H_)/8, 256>>>(P.v, 0);

    // 4) recurrence -> o, final state
    deltarec_k<<<dim3(16, H_, B_), 128>>>(P.q, P.k, P.v, P.ba, st0, P.o, stO);

    // 5) y = x + o @ wo
    split_k<<<2048, 256>>>(P.o, P.oh, P.ol, X_ELEMS/4);
    hgemm_k<<<dim3(D_/128, M_/128), 256, HG_SMEM>>>(P.oh, P.ol, P.woh, P.wol, x, y, M_, D_, D_);

    // 6) yn = rmsnorm(y); h1 = yn@w_gate; h2 = yn@w_up
    rmsnorm_k<<<M_, 256>>>(y, P.xn);
    split_k<<<2048, 256>>>(P.xn, P.xh, P.xl, X_ELEMS/4);
    hgemm_k<<<dim3(F_/128, M_/128), 256, HG_SMEM>>>(P.xh, P.xl, P.wgh, P.wgl, nullptr, P.h1, M_, F_, D_);
    hgemm_k<<<dim3(F_/128, M_/128), 256, HG_SMEM>>>(P.xh, P.xl, P.wuh, P.wul, nullptr, P.h2, M_, F_, D_);

    // 7) h1 = silu(h1)*h2 ; out = y + h1 @ w_down
    silumul_k<<<4096, 256>>>(P.h1, P.h2, (M_*F_)/4);
    split_k<<<4096, 256>>>(P.h1, P.xh, P.xl, (M_*F_)/4);
    hgemm_k<<<dim3(D_/128, M_/128), 256, HG_SMEM>>>(P.xh, P.xl, P.wdh, P.wdl, y, y, M_, D_, F_);
}